// round 1
// baseline (speedup 1.0000x reference)
#include <cuda_runtime.h>
#include <cuda_bf16.h>

// Soft-permutation matrices: g_P[0] = soft_perm(W1), g_P[1] = soft_perm(W2).
// Layout: g_P[w][i*10+j] = P[i][j] so l[i] = sum_j p[j] * P[i][j].
__device__ float g_P[2][100];

__global__ void prep_softperm_kernel(const float* __restrict__ W1,
                                     const float* __restrict__ W2) {
    int t = threadIdx.x;
    if (t < 20) {
        const float* W = (t < 10) ? W1 : W2;
        int r = t % 10;
        float row[10];
        float lo = 1e30f, hi = -1e30f;
#pragma unroll
        for (int j = 0; j < 10; ++j) {
            row[j] = W[r * 10 + j];
            lo = fminf(lo, row[j]);
            hi = fmaxf(hi, row[j]);
        }
        float invr = 1.0f / (hi - lo + 1e-8f);
        float s = 0.0f;
#pragma unroll
        for (int j = 0; j < 10; ++j) {
            row[j] = (row[j] - lo) * invr;
            s += row[j];
        }
        float invs = 1.0f / (s + 1e-8f);
#pragma unroll
        for (int j = 0; j < 10; ++j)
            g_P[t / 10][r * 10 + j] = row[j] * invs;
    }
}

// One thread = one row b. ROWS rows per block.
// y_k = 1 - prod_{i+j=k} max(u_i, v_j), u_i = clip(1-l1_i), v_j = clip(1-l2_j)
// then normalize. Mathematically identical (to ~1e-11) to the log/exp reference
// but with zero MUFU log/exp.
constexpr int ROWS = 256;

__global__ __launch_bounds__(ROWS, 1)
void bacon_fused_kernel(const float* __restrict__ p1,
                        const float* __restrict__ p2,
                        float* __restrict__ out,
                        int B) {
    // sb holds the staged p1 (2560 f) + p2 (2560 f); reused for out (4864 f <= 5120)
    __shared__ float sb[5120];
    __shared__ float sP[200];

    const int tid = threadIdx.x;
    const int row0 = blockIdx.x * ROWS;
    const int nrows = min(ROWS, B - row0);

    if (tid < 200) sP[tid] = ((const float*)g_P)[tid];

    if (nrows == ROWS) {
        // fast path: fully coalesced float4 staging (ROWS*10*4 = 10240 B, 16B aligned)
        const float4* p1v = (const float4*)(p1 + (size_t)row0 * 10);
        const float4* p2v = (const float4*)(p2 + (size_t)row0 * 10);
        float4* s1v = (float4*)sb;
        float4* s2v = (float4*)(sb + 2560);
#pragma unroll
        for (int i = tid; i < 640; i += ROWS) {
            s1v[i] = p1v[i];
            s2v[i] = p2v[i];
        }
    } else {
        int nfl = nrows * 10;
        for (int i = tid; i < nfl; i += ROWS) {
            sb[i]        = p1[(size_t)row0 * 10 + i];
            sb[2560 + i] = p2[(size_t)row0 * 10 + i];
        }
    }
    __syncthreads();

    float res[19];
    const bool active = (tid < nrows);

    if (active) {
        float a[10], b[10];
#pragma unroll
        for (int j = 0; j < 10; ++j) {
            a[j] = sb[tid * 10 + j];
            b[j] = sb[2560 + tid * 10 + j];
        }

        float u[10], v[10];
#pragma unroll
        for (int i = 0; i < 10; ++i) {
            float l1 = 0.0f, l2 = 0.0f;
#pragma unroll
            for (int j = 0; j < 10; ++j) {
                l1 = fmaf(a[j], sP[i * 10 + j], l1);
                l2 = fmaf(b[j], sP[100 + i * 10 + j], l2);
            }
            u[i] = fminf(fmaxf(1.0f - l1, 1e-6f), 1.0f - 1e-6f);
            v[i] = fminf(fmaxf(1.0f - l2, 1e-6f), 1.0f - 1e-6f);
        }

        float prod[19];
#pragma unroll
        for (int k = 0; k < 19; ++k) prod[k] = 1.0f;
#pragma unroll
        for (int i = 0; i < 10; ++i) {
#pragma unroll
            for (int j = 0; j < 10; ++j) {
                prod[i + j] *= fmaxf(u[i], v[j]);
            }
        }

        float s = 0.0f;
#pragma unroll
        for (int k = 0; k < 19; ++k) {
            res[k] = 1.0f - prod[k];
            s += res[k];
        }
        float inv = __fdividef(1.0f, s + 1e-9f);
#pragma unroll
        for (int k = 0; k < 19; ++k) res[k] *= inv;
    }

    // stage results through shared for coalesced float4 stores
    __syncthreads();
    if (active) {
#pragma unroll
        for (int k = 0; k < 19; ++k) sb[tid * 19 + k] = res[k];  // stride 19 (odd): conflict-free
    }
    __syncthreads();

    if (nrows == ROWS) {
        float4* ov = (float4*)(out + (size_t)row0 * 19);  // ROWS*19*4 = 19456 B, 16B aligned
        const float4* sbv = (const float4*)sb;
#pragma unroll
        for (int i = tid; i < 1216; i += ROWS) ov[i] = sbv[i];
    } else {
        int nfl = nrows * 19;
        for (int i = tid; i < nfl; i += ROWS)
            out[(size_t)row0 * 19 + i] = sb[i];
    }
}

extern "C" void kernel_launch(void* const* d_in, const int* in_sizes, int n_in,
                              void* d_out, int out_size) {
    const float* p1 = (const float*)d_in[0];
    const float* p2 = (const float*)d_in[1];
    const float* W1 = (const float*)d_in[2];
    const float* W2 = (const float*)d_in[3];
    float* out = (float*)d_out;

    int B = in_sizes[0] / 10;

    prep_softperm_kernel<<<1, 32>>>(W1, W2);

    int blocks = (B + ROWS - 1) / ROWS;
    bacon_fused_kernel<<<blocks, ROWS>>>(p1, p2, out, B);
}

// round 2
// speedup vs baseline: 1.0252x; 1.0252x over previous
#include <cuda_runtime.h>
#include <cuda_bf16.h>

// Transposed soft-perm matrices: g_Pt[w][j][i] = P_w[i][j], row stride 12 floats
// (48B, 16B-aligned) so pairs (i,i+1) are adjacent for f32x2 FMA.
__device__ float g_Pt[2][10][12];

__global__ void prep_softperm_kernel(const float* __restrict__ W1,
                                     const float* __restrict__ W2) {
    int t = threadIdx.x;
    if (t < 20) {
        const float* W = (t < 10) ? W1 : W2;
        int r = t % 10;
        int w = t / 10;
        float row[10];
        float lo = 1e30f, hi = -1e30f;
#pragma unroll
        for (int j = 0; j < 10; ++j) {
            row[j] = W[r * 10 + j];
            lo = fminf(lo, row[j]);
            hi = fmaxf(hi, row[j]);
        }
        float invr = 1.0f / (hi - lo + 1e-8f);
        float s = 0.0f;
#pragma unroll
        for (int j = 0; j < 10; ++j) {
            row[j] = (row[j] - lo) * invr;
            s += row[j];
        }
        float invs = 1.0f / (s + 1e-8f);
#pragma unroll
        for (int j = 0; j < 10; ++j)
            g_Pt[w][j][r] = row[j] * invs;   // transposed store
    }
}

using u64 = unsigned long long;

__device__ __forceinline__ void fma2(u64& d, u64 a, u64 b) {
    asm("fma.rn.f32x2 %0, %1, %2, %0;" : "+l"(d) : "l"(a), "l"(b));
}
__device__ __forceinline__ u64 fma2n(u64 a, u64 b, u64 c) {
    u64 d;
    asm("fma.rn.f32x2 %0, %1, %2, %3;" : "=l"(d) : "l"(a), "l"(b), "l"(c));
    return d;
}
__device__ __forceinline__ u64 pack2(float x, float y) {
    u64 d;
    asm("mov.b64 %0, {%1, %2};" : "=l"(d) : "f"(x), "f"(y));
    return d;
}
__device__ __forceinline__ void unpack2(u64 v, float& x, float& y) {
    asm("mov.b64 {%0, %1}, %2;" : "=f"(x), "=f"(y) : "l"(v));
}
__device__ __forceinline__ void cp_async16(void* smem, const void* gmem) {
    unsigned s = (unsigned)__cvta_generic_to_shared(smem);
    asm volatile("cp.async.cg.shared.global [%0], [%1], 16;" :: "r"(s), "l"(gmem));
}
__device__ __forceinline__ void cp_commit() {
    asm volatile("cp.async.commit_group;");
}
template <int N>
__device__ __forceinline__ void cp_wait() {
    asm volatile("cp.async.wait_group %0;" :: "n"(N));
}

constexpr int TILE = 256;   // rows per tile (== blockDim.x)

__global__ __launch_bounds__(TILE, 4)
void bacon_fused_kernel(const float* __restrict__ p1,
                        const float* __restrict__ p2,
                        float* __restrict__ out,
                        int B, int ntiles) {
    // double-buffered input staging; each buffer also reused for output staging
    __shared__ __align__(16) float sb[2][5120];
    __shared__ __align__(16) float sPt[2][10][12];

    const int tid = threadIdx.x;
    const int G = gridDim.x;

    // load transposed P into shared (240 floats)
    if (tid < 240) ((float*)sPt)[tid] = ((const float*)g_Pt)[tid];

    auto load_tile = [&](int buf, int t) {
        size_t base = (size_t)t * TILE * 10;
        int rows = min(TILE, B - t * TILE);
        float* s = sb[buf];
        if (rows == TILE) {
            const float4* g1 = (const float4*)(p1 + base);
            const float4* g2 = (const float4*)(p2 + base);
#pragma unroll
            for (int i = tid; i < 640; i += TILE) {
                cp_async16(&s[i * 4], &g1[i]);
                cp_async16(&s[2560 + i * 4], &g2[i]);
            }
        } else {
            int n = rows * 10;
            for (int i = tid; i < n; i += TILE) {
                s[i] = p1[base + i];
                s[2560 + i] = p2[base + i];
            }
        }
    };

    int t0 = blockIdx.x;
    if (t0 >= ntiles) return;

    load_tile(0, t0);
    cp_commit();

    int p = 0;
    for (int t = t0; t < ntiles; t += G) {
        int tn = t + G;
        if (tn < ntiles) {
            load_tile(1 - p, tn);
            cp_commit();
            cp_wait<1>();     // current tile's group done; next may be in flight
        } else {
            cp_wait<0>();
        }
        __syncthreads();

        const int nrows = min(TILE, B - t * TILE);
        const bool active = (tid < nrows);
        const float* s = sb[p];

        float u[10], v[10];
        float prod[19];

        if (active) {
            // matmul: l1 = a . P1^T, l2 = b . P2^T, using packed f32x2 FMA.
            // acc1[q] packs (l1[2q], l1[2q+1]); same for acc2.
            u64 acc1[5], acc2[5];
#pragma unroll
            for (int q = 0; q < 5; ++q) { acc1[q] = 0ULL; acc2[q] = 0ULL; }

#pragma unroll
            for (int jj = 0; jj < 5; ++jj) {
                float2 av = *(const float2*)&s[tid * 10 + jj * 2];
                float2 bv = *(const float2*)&s[2560 + tid * 10 + jj * 2];
#pragma unroll
                for (int h = 0; h < 2; ++h) {
                    int j = jj * 2 + h;
                    float aj = h ? av.y : av.x;
                    float bj = h ? bv.y : bv.x;
                    u64 a2 = pack2(aj, aj);
                    u64 b2 = pack2(bj, bj);
                    // P rows (broadcast LDS.128/LDS.64 from shared)
                    const ulonglong2* r1 = (const ulonglong2*)&sPt[0][j][0];
                    const ulonglong2* r2 = (const ulonglong2*)&sPt[1][j][0];
                    ulonglong2 p01 = r1[0], p23 = r1[1];
                    u64 p4 = ((const u64*)&sPt[0][j][0])[4];
                    ulonglong2 q01 = r2[0], q23 = r2[1];
                    u64 q4 = ((const u64*)&sPt[1][j][0])[4];
                    fma2(acc1[0], a2, p01.x);
                    fma2(acc1[1], a2, p01.y);
                    fma2(acc1[2], a2, p23.x);
                    fma2(acc1[3], a2, p23.y);
                    fma2(acc1[4], a2, p4);
                    fma2(acc2[0], b2, q01.x);
                    fma2(acc2[1], b2, q01.y);
                    fma2(acc2[2], b2, q23.x);
                    fma2(acc2[3], b2, q23.y);
                    fma2(acc2[4], b2, q4);
                }
            }

            // u_i = clip(1 - l1_i), v_i = clip(1 - l2_i); (1-l) via one FFMA2/pair
            const u64 NEG1 = pack2(-1.0f, -1.0f);
            const u64 ONE1 = pack2(1.0f, 1.0f);
#pragma unroll
            for (int q = 0; q < 5; ++q) {
                float x, y;
                unpack2(fma2n(acc1[q], NEG1, ONE1), x, y);
                u[2 * q]     = fminf(fmaxf(x, 1e-6f), 1.0f - 1e-6f);
                u[2 * q + 1] = fminf(fmaxf(y, 1e-6f), 1.0f - 1e-6f);
                unpack2(fma2n(acc2[q], NEG1, ONE1), x, y);
                v[2 * q]     = fminf(fmaxf(x, 1e-6f), 1.0f - 1e-6f);
                v[2 * q + 1] = fminf(fmaxf(y, 1e-6f), 1.0f - 1e-6f);
            }

            // y_k = 1 - prod_{i+j=k} max(u_i, v_j)
#pragma unroll
            for (int k = 0; k < 19; ++k) prod[k] = 1.0f;
#pragma unroll
            for (int i = 0; i < 10; ++i) {
#pragma unroll
                for (int j = 0; j < 10; ++j)
                    prod[i + j] *= fmaxf(u[i], v[j]);
            }

            float sum = 0.0f;
#pragma unroll
            for (int k = 0; k < 19; ++k) {
                prod[k] = 1.0f - prod[k];
                sum += prod[k];
            }
            float inv = __fdividef(1.0f, sum + 1e-9f);
#pragma unroll
            for (int k = 0; k < 19; ++k) prod[k] *= inv;
        }

        __syncthreads();   // all reads of sb[p] done -> reuse for output staging
        if (active) {
#pragma unroll
            for (int k = 0; k < 19; ++k)
                sb[p][tid * 19 + k] = prod[k];   // stride 19: conflict-free
        }
        __syncthreads();

        float* ob = out + (size_t)t * TILE * 19;
        if (nrows == TILE) {
            float4* ov = (float4*)ob;
            const float4* sv = (const float4*)sb[p];
#pragma unroll
            for (int i = tid; i < 1216; i += TILE) ov[i] = sv[i];
        } else {
            int n = nrows * 19;
            for (int i = tid; i < n; i += TILE) ob[i] = sb[p][i];
        }
        __syncthreads();   // stores read sb[p] before next prefetch overwrites it
        p ^= 1;
    }
}

extern "C" void kernel_launch(void* const* d_in, const int* in_sizes, int n_in,
                              void* d_out, int out_size) {
    const float* p1 = (const float*)d_in[0];
    const float* p2 = (const float*)d_in[1];
    const float* W1 = (const float*)d_in[2];
    const float* W2 = (const float*)d_in[3];
    float* out = (float*)d_out;

    int B = in_sizes[0] / 10;
    int ntiles = (B + TILE - 1) / TILE;

    prep_softperm_kernel<<<1, 32>>>(W1, W2);

    // persistent-ish grid: ~2 tiles per block when large, single wave at occ 4
    int G = ntiles;
    if ((ntiles + 1) / 2 <= 592) G = (ntiles + 1) / 2;
    if (G > 592) G = 592;
    if (G < 1) G = 1;

    bacon_fused_kernel<<<G, TILE>>>(p1, p2, out, B, ntiles);
}